// round 1
// baseline (speedup 1.0000x reference)
#include <cuda_runtime.h>
#include <math.h>

#define H 1024
#define V 32000
#define L 4096

// ---------------- scratch (no allocations allowed) ----------------
__device__ float g_q[H];        // wW@h0 + wb + ub
__device__ float g_scores[L];
__device__ float g_attn[L];
__device__ float g_context[H];
__device__ float g_x[H];        // relu(cW@[ctx;emb]+cb)
__device__ float g_gi[3 * H];
__device__ float g_gh[3 * H];
__device__ float g_ov[H];       // context + h_new

__device__ __forceinline__ float warp_sum(float v) {
#pragma unroll
    for (int o = 16; o; o >>= 1) v += __shfl_xor_sync(0xffffffffu, v, o);
    return v;
}

// ---------------- K0: zero accumulators ----------------
__global__ void k_zero() {
    int t = blockIdx.x * blockDim.x + threadIdx.x;
    if (t < L) g_scores[t] = 0.f;
    if (t < H) g_context[t] = 0.f;
}

// ---------------- K1: q = wW @ h0 + wb + ub  (warp per row) ----------------
__global__ void k1_q(const float* __restrict__ h0, const float* __restrict__ wW,
                     const float* __restrict__ wb, const float* __restrict__ ub) {
    int warp = (blockIdx.x * blockDim.x + threadIdx.x) >> 5;
    int lane = threadIdx.x & 31;
    if (warp >= H) return;
    const float4* row = (const float4*)(wW + (size_t)warp * H);
    const float4* h4 = (const float4*)h0;
    float s = 0.f;
#pragma unroll
    for (int i = 0; i < 8; i++) {
        float4 a = row[lane + 32 * i];
        float4 b = h4[lane + 32 * i];
        s += a.x * b.x + a.y * b.y + a.z * b.z + a.w * b.w;
    }
    s = warp_sum(s);
    if (lane == 0) g_q[warp] = s + wb[warp] + ub[warp];
}

// ---------------- K2: fused scores GEMM ----------------
// scores[l] += sum_{n in tile} vW[n] * tanh(q[n] + sum_k enc[l,k]*uW[n,k])
// 64x64 tile, Kc=32, 256 threads, 4x4 micro-tile, XOR-swizzled SMEM.
#define TM 64
#define TN 64
#define TK 32

__global__ void __launch_bounds__(256) k2_scores(const float* __restrict__ enc,
                                                 const float* __restrict__ uW,
                                                 const float* __restrict__ vW) {
    __shared__ float As[TK * TM];
    __shared__ float Bs[TK * TN];
    __shared__ float red[TM];
    int tid = threadIdx.x;
    int tx = tid & 15, ty = tid >> 4;
    int bm = blockIdx.x * TM;
    int bn = blockIdx.y * TN;
    float acc[4][4] = {};

    int lrow = tid >> 3;        // 0..31
    int lk = (tid & 7) * 4;     // 0,4,...,28

    for (int kb = 0; kb < H; kb += TK) {
#pragma unroll
        for (int i = 0; i < 2; i++) {
            int row = lrow + 32 * i;
            float4 a = *(const float4*)(enc + (size_t)(bm + row) * H + kb + lk);
            float4 b = *(const float4*)(uW + (size_t)(bn + row) * H + kb + lk);
            int g = row >> 3, r = row & 7;
#pragma unroll
            for (int j = 0; j < 4; j++) {
                int kk = lk + j;
                int pg = g ^ (kk >> 2);           // group swizzle: 2-way STS max
                As[kk * TM + pg * 8 + r] = ((const float*)&a)[j];
                Bs[kk * TN + pg * 8 + r] = ((const float*)&b)[j];
            }
        }
        __syncthreads();
#pragma unroll
        for (int k = 0; k < TK; k++) {
            int s = k >> 2;
            float4 av = *(const float4*)(As + k * TM + (((ty >> 1) ^ s) * 8) + (ty & 1) * 4);
            float4 bv = *(const float4*)(Bs + k * TN + (((tx >> 1) ^ s) * 8) + (tx & 1) * 4);
            float a[4] = {av.x, av.y, av.z, av.w};
            float b[4] = {bv.x, bv.y, bv.z, bv.w};
#pragma unroll
            for (int i = 0; i < 4; i++)
#pragma unroll
                for (int j = 0; j < 4; j++) acc[i][j] += a[i] * b[j];
        }
        __syncthreads();
    }

    // epilogue: weighted tanh row-sum, block reduce, atomic into g_scores
    float vv[4], qq[4];
#pragma unroll
    for (int j = 0; j < 4; j++) {
        int n = bn + tx * 4 + j;
        vv[j] = vW[n];
        qq[j] = g_q[n];
    }
    if (tid < TM) red[tid] = 0.f;
    __syncthreads();
#pragma unroll
    for (int i = 0; i < 4; i++) {
        float p = 0.f;
#pragma unroll
        for (int j = 0; j < 4; j++) p += vv[j] * tanhf(qq[j] + acc[i][j]);
        atomicAdd(&red[ty * 4 + i], p);
    }
    __syncthreads();
    if (tid < TM) atomicAdd(&g_scores[bm + tid], red[tid]);
}

// ---------------- K3: softmax over L=4096 (one block) ----------------
__global__ void k3_softmax(float* __restrict__ out_attn) {
    __shared__ float sm[32];
    int t = threadIdx.x;
    float v[4];
    float mx = -1e30f;
#pragma unroll
    for (int i = 0; i < 4; i++) {
        v[i] = g_scores[t + 1024 * i];
        mx = fmaxf(mx, v[i]);
    }
#pragma unroll
    for (int o = 16; o; o >>= 1) mx = fmaxf(mx, __shfl_xor_sync(0xffffffffu, mx, o));
    if ((t & 31) == 0) sm[t >> 5] = mx;
    __syncthreads();
    if (t < 32) {
        float m = sm[t];
#pragma unroll
        for (int o = 16; o; o >>= 1) m = fmaxf(m, __shfl_xor_sync(0xffffffffu, m, o));
        if (t == 0) sm[0] = m;
    }
    __syncthreads();
    mx = sm[0];
    __syncthreads();
    float se = 0.f;
#pragma unroll
    for (int i = 0; i < 4; i++) {
        v[i] = expf(v[i] - mx);
        se += v[i];
    }
    se = warp_sum(se);
    if ((t & 31) == 0) sm[t >> 5] = se;
    __syncthreads();
    if (t < 32) {
        float s2 = sm[t];
        s2 = warp_sum(s2);
        if (t == 0) sm[0] = s2;
    }
    __syncthreads();
    float inv = 1.f / sm[0];
#pragma unroll
    for (int i = 0; i < 4; i++) {
        float a = v[i] * inv;
        g_attn[t + 1024 * i] = a;
        out_attn[t + 1024 * i] = a;
    }
}

// ---------------- K4: context = attn^T @ enc ----------------
__global__ void k4_context(const float* __restrict__ enc) {
    __shared__ float aw[64];
    int t = threadIdx.x;
    int l0 = blockIdx.x * 64;
    if (t < 64) aw[t] = g_attn[l0 + t];
    __syncthreads();
    float s = 0.f;
#pragma unroll 8
    for (int l = 0; l < 64; l++) s += aw[l] * enc[(size_t)(l0 + l) * H + t];
    atomicAdd(&g_context[t], s);
}

// ---------------- K5: x = relu(cW @ [context;embedded] + cb) ----------------
__global__ void k5_combine(const float* __restrict__ cW, const float* __restrict__ cb,
                           const float* __restrict__ emb, const int* __restrict__ tok) {
    int warp = (blockIdx.x * blockDim.x + threadIdx.x) >> 5;
    int lane = threadIdx.x & 31;
    if (warp >= H) return;
    const float4* r1 = (const float4*)(cW + (size_t)warp * 2 * H);
    const float4* r2 = r1 + H / 4;
    const float4* c4 = (const float4*)g_context;
    const float4* e4 = (const float4*)(emb + (size_t)tok[0] * H);
    float s = 0.f;
#pragma unroll
    for (int i = 0; i < 8; i++) {
        float4 a = r1[lane + 32 * i];
        float4 b = c4[lane + 32 * i];
        s += a.x * b.x + a.y * b.y + a.z * b.z + a.w * b.w;
        float4 a2 = r2[lane + 32 * i];
        float4 b2 = e4[lane + 32 * i];
        s += a2.x * b2.x + a2.y * b2.y + a2.z * b2.z + a2.w * b2.w;
    }
    s = warp_sum(s);
    if (lane == 0) g_x[warp] = fmaxf(s + cb[warp], 0.f);
}

// ---------------- K6: gi = w_ih@x + b_ih ; gh = w_hh@hprev + b_hh ----------------
__global__ void k6_gru_gemv(const float* __restrict__ w_ih, const float* __restrict__ b_ih,
                            const float* __restrict__ w_hh, const float* __restrict__ b_hh,
                            const float* __restrict__ hprev) {
    int warp = (blockIdx.x * blockDim.x + threadIdx.x) >> 5;
    int lane = threadIdx.x & 31;
    if (warp >= 6 * H) return;
    const float4* row;
    const float4* vec;
    float bias;
    float* out;
    int idx;
    if (warp < 3 * H) {
        idx = warp;
        row = (const float4*)(w_ih + (size_t)idx * H);
        vec = (const float4*)g_x;
        bias = b_ih[idx];
        out = g_gi;
    } else {
        idx = warp - 3 * H;
        row = (const float4*)(w_hh + (size_t)idx * H);
        vec = (const float4*)hprev;
        bias = b_hh[idx];
        out = g_gh;
    }
    float s = 0.f;
#pragma unroll
    for (int i = 0; i < 8; i++) {
        float4 a = row[lane + 32 * i];
        float4 b = vec[lane + 32 * i];
        s += a.x * b.x + a.y * b.y + a.z * b.z + a.w * b.w;
    }
    s = warp_sum(s);
    if (lane == 0) out[idx] = s + bias;
}

// ---------------- K7: GRU gates + residual vector ----------------
__global__ void k7_gru(const float* __restrict__ hprev, float* __restrict__ d_out) {
    int i = threadIdx.x;
    float r = 1.f / (1.f + expf(-(g_gi[i] + g_gh[i])));
    float z = 1.f / (1.f + expf(-(g_gi[H + i] + g_gh[H + i])));
    float n = tanhf(g_gi[2 * H + i] + r * g_gh[2 * H + i]);
    float hp = hprev[i];
    float h = (1.f - z) * n + z * hp;
    d_out[V + i] = h;           // new_hidden output
    g_ov[i] = g_context[i] + h; // residual
}

// ---------------- K8: logits = outW @ ov + outb (warp per row) ----------------
__global__ void __launch_bounds__(256) k8_logits(const float* __restrict__ outW,
                                                 const float* __restrict__ outb,
                                                 float* __restrict__ d_out) {
    __shared__ float4 ov[H / 4];
    int t = threadIdx.x;
    ov[t] = ((const float4*)g_ov)[t];
    __syncthreads();
    int warp = t >> 5, lane = t & 31;
    int v = blockIdx.x * 8 + warp;
    const float4* w4 = (const float4*)(outW + (size_t)v * H);
    float s = 0.f;
#pragma unroll
    for (int i = 0; i < 8; i++) {
        float4 a = w4[lane + 32 * i];
        float4 b = ov[lane + 32 * i];
        s += a.x * b.x + a.y * b.y + a.z * b.z + a.w * b.w;
    }
    s = warp_sum(s);
    if (lane == 0) d_out[v] = s + outb[v];
}

// ---------------- launch ----------------
extern "C" void kernel_launch(void* const* d_in, const int* in_sizes, int n_in,
                              void* d_out, int out_size) {
    const int* tok = (const int*)d_in[0];
    const float* hidden = (const float*)d_in[1];
    const float* enc = (const float*)d_in[2];
    const float* emb = (const float*)d_in[3];
    const float* wW = (const float*)d_in[4];
    const float* wb = (const float*)d_in[5];
    const float* uW = (const float*)d_in[6];
    const float* ub = (const float*)d_in[7];
    const float* vW = (const float*)d_in[8];
    const float* cW = (const float*)d_in[9];
    const float* cb = (const float*)d_in[10];
    const float* w_ih = (const float*)d_in[11];
    const float* b_ih = (const float*)d_in[12];
    const float* w_hh = (const float*)d_in[13];
    const float* b_hh = (const float*)d_in[14];
    const float* outW = (const float*)d_in[15];
    const float* outb = (const float*)d_in[16];
    float* out = (float*)d_out;

    k_zero<<<5, 1024>>>();
    k1_q<<<128, 256>>>(hidden, wW, wb, ub);
    k2_scores<<<dim3(L / TM, H / TN), 256>>>(enc, uW, vW);
    k3_softmax<<<1, 1024>>>(out + V + H);
    k4_context<<<L / 64, 1024>>>(enc);
    k5_combine<<<128, 256>>>(cW, cb, emb, tok);
    k6_gru_gemv<<<(6 * H) / 8, 256>>>(w_ih, b_ih, w_hh, b_hh, hidden);
    k7_gru<<<1, 1024>>>(hidden, out);
    k8_logits<<<V / 8, 256>>>(outW, outb, out);
}

// round 3
// speedup vs baseline: 1.9352x; 1.9352x over previous
#include <cuda_runtime.h>
#include <cuda_bf16.h>
#include <math.h>
#include <stdint.h>

#define H 1024
#define V 32000
#define L 4096
#define KP 3072          // expanded K: 3 bf16 terms per fp32
#define NC 48            // K chunks of 64 bf16
#define NT 8             // N tiles (1024/128)

// ---------------- device scratch ----------------
__device__ __nv_bfloat16 g_encb[(size_t)L * KP];   // 24 MB
__device__ __nv_bfloat16 g_uWb[(size_t)H * KP];    // 6 MB
__device__ float g_spart[NT * L];
__device__ float g_q[H];
__device__ float g_attn[L];
__device__ float g_context[H];
__device__ float g_x[H];
__device__ float g_gi[3 * H];
__device__ float g_gh[3 * H];
__device__ float g_ov[H];

// ---------------- helpers ----------------
__device__ __forceinline__ uint32_t smem_u32(const void* p) {
    uint32_t a;
    asm("{ .reg .u64 t; cvta.to.shared.u64 t, %1; cvt.u32.u64 %0, t; }" : "=r"(a) : "l"(p));
    return a;
}
__device__ __forceinline__ uint32_t sw(uint32_t off) {   // Swizzle<3,4,3> on 128B rows
    return off ^ ((off >> 3) & 0x70u);
}
#define CP_ASYNC16(dst, src) \
    asm volatile("cp.async.cg.shared.global [%0], [%1], 16;" :: "r"(dst), "l"(src) : "memory")
#define CP_COMMIT() asm volatile("cp.async.commit_group;" ::: "memory")
#define CP_WAIT(n)  asm volatile("cp.async.wait_group %0;" :: "n"(n) : "memory")
#define LDSM_X4(r, a) \
    asm volatile("ldmatrix.sync.aligned.m8n8.x4.shared.b16 {%0,%1,%2,%3}, [%4];" \
                 : "=r"((r)[0]), "=r"((r)[1]), "=r"((r)[2]), "=r"((r)[3]) : "r"(a))

__device__ __forceinline__ void mma_bf16(float* c, const uint32_t* a, uint32_t b0, uint32_t b1) {
    asm volatile("mma.sync.aligned.m16n8k16.row.col.f32.bf16.bf16.f32 "
                 "{%0,%1,%2,%3}, {%4,%5,%6,%7}, {%8,%9}, {%0,%1,%2,%3};"
                 : "+f"(c[0]), "+f"(c[1]), "+f"(c[2]), "+f"(c[3])
                 : "r"(a[0]), "r"(a[1]), "r"(a[2]), "r"(a[3]), "r"(b0), "r"(b1));
}

__device__ __forceinline__ float warp_sum(float v) {
#pragma unroll
    for (int o = 16; o; o >>= 1) v += __shfl_xor_sync(0xffffffffu, v, o);
    return v;
}

// ---------------- conversion: fp32 -> 3-term bf16 split ----------------
// A (enc): pattern [hi, hi, lo];  B (uW): pattern [hi, lo, hi]
// so bf16 GEMM over K'=3072 computes hi*hi + hi*lo + lo*hi.
__global__ void k_conv_enc(const float* __restrict__ src) {
    int i = blockIdx.x * blockDim.x + threadIdx.x;   // over L*H
    float x = src[i];
    __nv_bfloat16 hi = __float2bfloat16(x);
    __nv_bfloat16 lo = __float2bfloat16(x - __bfloat162float(hi));
    int row = i >> 10, k = i & 1023;
    size_t b = (size_t)row * KP + 3 * k;
    g_encb[b] = hi; g_encb[b + 1] = hi; g_encb[b + 2] = lo;
}
__global__ void k_conv_uW(const float* __restrict__ src) {
    int i = blockIdx.x * blockDim.x + threadIdx.x;   // over H*H
    float x = src[i];
    __nv_bfloat16 hi = __float2bfloat16(x);
    __nv_bfloat16 lo = __float2bfloat16(x - __bfloat162float(hi));
    int row = i >> 10, k = i & 1023;
    size_t b = (size_t)row * KP + 3 * k;
    g_uWb[b] = hi; g_uWb[b + 1] = lo; g_uWb[b + 2] = hi;
}

// ---------------- K0: zero context accumulator ----------------
__global__ void k_zero() {
    int t = threadIdx.x;
    if (t < H) g_context[t] = 0.f;
}

// ---------------- K1: q = wW @ h0 + wb + ub ----------------
__global__ void k1_q(const float* __restrict__ h0, const float* __restrict__ wW,
                     const float* __restrict__ wb, const float* __restrict__ ub) {
    int warp = (blockIdx.x * blockDim.x + threadIdx.x) >> 5;
    int lane = threadIdx.x & 31;
    if (warp >= H) return;
    const float4* row = (const float4*)(wW + (size_t)warp * H);
    const float4* h4 = (const float4*)h0;
    float s = 0.f;
#pragma unroll
    for (int i = 0; i < 8; i++) {
        float4 a = row[lane + 32 * i];
        float4 b = h4[lane + 32 * i];
        s += a.x * b.x + a.y * b.y + a.z * b.z + a.w * b.w;
    }
    s = warp_sum(s);
    if (lane == 0) g_q[warp] = s + wb[warp] + ub[warp];
}

// ---------------- K2: mma.sync scores GEMM ----------------
// S_part[bn][l] = sum_{n in tile} vW[n]*tanh(q[n] + enc[l,:]·uW[n,:])
// 128x128 tile, Kc=64 bf16, cp.async double buffer, 8 warps 4x2, warp=32x64.
#define SMEM_DYN (2 * 32768 + 1024)

__global__ void __launch_bounds__(256, 2) k2_scores(const float* __restrict__ vW) {
    extern __shared__ char dsm[];
    __shared__ float sq[128], sv[128], sred[128][2];

    uint32_t sbase = (smem_u32(dsm) + 1023u) & ~1023u;
    int tid = threadIdx.x, wid = tid >> 5, lane = tid & 31;
    int wm = wid & 3, wn = wid >> 2;
    int bm = blockIdx.x * 128, bn = blockIdx.y * 128;

    if (tid < 128) { sq[tid] = g_q[bn + tid]; sv[tid] = vW[bn + tid]; }

    const __nv_bfloat16* gA = g_encb + (size_t)bm * KP;
    const __nv_bfloat16* gB = g_uWb + (size_t)bn * KP;

    // per-thread load slots: idx = tid + 256*i -> (row, 16B-chunk)
    int lr[4], lc[4];
    uint32_t loff[4];
#pragma unroll
    for (int i = 0; i < 4; i++) {
        int idx = tid + 256 * i;
        lr[i] = idx >> 3;
        lc[i] = idx & 7;
        loff[i] = sw((uint32_t)(lr[i] * 128 + lc[i] * 16));
    }

#define LOAD_CHUNK(c, buf) do { \
    uint32_t s_ = sbase + (buf) * 32768u; \
    _Pragma("unroll") \
    for (int i_ = 0; i_ < 4; i_++) { \
        const __nv_bfloat16* a_ = gA + (size_t)lr[i_] * KP + (c) * 64 + lc[i_] * 8; \
        const __nv_bfloat16* b_ = gB + (size_t)lr[i_] * KP + (c) * 64 + lc[i_] * 8; \
        CP_ASYNC16(s_ + loff[i_], a_); \
        CP_ASYNC16(s_ + 16384u + loff[i_], b_); \
    } \
    CP_COMMIT(); \
} while (0)

    float acc[2][8][4] = {};

    LOAD_CHUNK(0, 0);

    // ldmatrix lane-address components (row within tile, k-halves)
    uint32_t aRow[2], bRow[4];
#pragma unroll
    for (int mt = 0; mt < 2; mt++)
        aRow[mt] = (uint32_t)((wm * 32 + mt * 16 + (lane & 15)) * 128 + (lane >> 4) * 16);
#pragma unroll
    for (int bp = 0; bp < 4; bp++)
        bRow[bp] = (uint32_t)((wn * 64 + bp * 16 + (lane & 15)) * 128 + (lane >> 4) * 16);

    for (int c = 0; c < NC; c++) {
        if (c + 1 < NC) {
            LOAD_CHUNK(c + 1, (c + 1) & 1);
            CP_WAIT(1);
        } else {
            CP_WAIT(0);
        }
        __syncthreads();
        uint32_t sA = sbase + (uint32_t)(c & 1) * 32768u;
        uint32_t sB = sA + 16384u;
#pragma unroll
        for (int ks = 0; ks < 4; ks++) {
            uint32_t afr[2][4];
#pragma unroll
            for (int mt = 0; mt < 2; mt++)
                LDSM_X4(afr[mt], sA + sw(aRow[mt] + ks * 32));
            uint32_t bfr[4][4];
#pragma unroll
            for (int bp = 0; bp < 4; bp++)
                LDSM_X4(bfr[bp], sB + sw(bRow[bp] + ks * 32));
#pragma unroll
            for (int mt = 0; mt < 2; mt++)
#pragma unroll
                for (int nt = 0; nt < 8; nt++) {
                    uint32_t b0 = bfr[nt >> 1][nt & 1];
                    uint32_t b1 = bfr[nt >> 1][(nt & 1) + 2];
                    mma_bf16(acc[mt][nt], afr[mt], b0, b1);
                }
        }
        __syncthreads();
    }

    // ---- epilogue: weighted tanh row reduction ----
    int cb = wn * 64;
    int c0 = 2 * (lane & 3);
    float p[2][2];
#pragma unroll
    for (int mt = 0; mt < 2; mt++)
#pragma unroll
        for (int half = 0; half < 2; half++) {
            float s = 0.f;
#pragma unroll
            for (int nt = 0; nt < 8; nt++) {
#pragma unroll
                for (int j = 0; j < 2; j++) {
                    int n = cb + nt * 8 + c0 + j;
                    s += sv[n] * tanhf(sq[n] + acc[mt][nt][half * 2 + j]);
                }
            }
            p[mt][half] = s;
        }
#pragma unroll
    for (int mt = 0; mt < 2; mt++)
#pragma unroll
        for (int half = 0; half < 2; half++) {
            float s = p[mt][half];
            s += __shfl_xor_sync(0xffffffffu, s, 1);
            s += __shfl_xor_sync(0xffffffffu, s, 2);
            p[mt][half] = s;
        }
    if ((lane & 3) == 0) {
#pragma unroll
        for (int mt = 0; mt < 2; mt++)
#pragma unroll
            for (int half = 0; half < 2; half++)
                sred[wm * 32 + mt * 16 + half * 8 + (lane >> 2)][wn] = p[mt][half];
    }
    __syncthreads();
    if (tid < 128)
        g_spart[blockIdx.y * L + bm + tid] = sred[tid][0] + sred[tid][1];
}

// ---------------- K3: sum partials + softmax ----------------
__global__ void k3_softmax(float* __restrict__ out_attn) {
    __shared__ float sm[32];
    int t = threadIdx.x;
    float v[4];
    float mx = -1e30f;
#pragma unroll
    for (int i = 0; i < 4; i++) {
        float s = 0.f;
#pragma unroll
        for (int nt = 0; nt < NT; nt++) s += g_spart[nt * L + t + 1024 * i];
        v[i] = s;
        mx = fmaxf(mx, s);
    }
#pragma unroll
    for (int o = 16; o; o >>= 1) mx = fmaxf(mx, __shfl_xor_sync(0xffffffffu, mx, o));
    if ((t & 31) == 0) sm[t >> 5] = mx;
    __syncthreads();
    if (t < 32) {
        float m2 = sm[t];
#pragma unroll
        for (int o = 16; o; o >>= 1) m2 = fmaxf(m2, __shfl_xor_sync(0xffffffffu, m2, o));
        if (t == 0) sm[0] = m2;
    }
    __syncthreads();
    mx = sm[0];
    __syncthreads();
    float se = 0.f;
#pragma unroll
    for (int i = 0; i < 4; i++) {
        v[i] = expf(v[i] - mx);
        se += v[i];
    }
    se = warp_sum(se);
    if ((t & 31) == 0) sm[t >> 5] = se;
    __syncthreads();
    if (t < 32) {
        float s2 = sm[t];
        s2 = warp_sum(s2);
        if (t == 0) sm[0] = s2;
    }
    __syncthreads();
    float inv = 1.f / sm[0];
#pragma unroll
    for (int i = 0; i < 4; i++) {
        float a = v[i] * inv;
        g_attn[t + 1024 * i] = a;
        out_attn[t + 1024 * i] = a;
    }
}

// ---------------- K4: context = attn^T @ enc ----------------
__global__ void k4_context(const float* __restrict__ enc) {
    __shared__ float aw[64];
    int t = threadIdx.x;
    int l0 = blockIdx.x * 64;
    if (t < 64) aw[t] = g_attn[l0 + t];
    __syncthreads();
    float s = 0.f;
#pragma unroll 8
    for (int l = 0; l < 64; l++) s += aw[l] * enc[(size_t)(l0 + l) * H + t];
    atomicAdd(&g_context[t], s);
}

// ---------------- K5: x = relu(cW @ [context;embedded] + cb) ----------------
__global__ void k5_combine(const float* __restrict__ cW, const float* __restrict__ cb,
                           const float* __restrict__ emb, const int* __restrict__ tok) {
    int warp = (blockIdx.x * blockDim.x + threadIdx.x) >> 5;
    int lane = threadIdx.x & 31;
    if (warp >= H) return;
    const float4* r1 = (const float4*)(cW + (size_t)warp * 2 * H);
    const float4* r2 = r1 + H / 4;
    const float4* c4 = (const float4*)g_context;
    const float4* e4 = (const float4*)(emb + (size_t)tok[0] * H);
    float s = 0.f;
#pragma unroll
    for (int i = 0; i < 8; i++) {
        float4 a = r1[lane + 32 * i];
        float4 b = c4[lane + 32 * i];
        s += a.x * b.x + a.y * b.y + a.z * b.z + a.w * b.w;
        float4 a2 = r2[lane + 32 * i];
        float4 b2 = e4[lane + 32 * i];
        s += a2.x * b2.x + a2.y * b2.y + a2.z * b2.z + a2.w * b2.w;
    }
    s = warp_sum(s);
    if (lane == 0) g_x[warp] = fmaxf(s + cb[warp], 0.f);
}

// ---------------- K6: GRU gate GEMVs ----------------
__global__ void k6_gru_gemv(const float* __restrict__ w_ih, const float* __restrict__ b_ih,
                            const float* __restrict__ w_hh, const float* __restrict__ b_hh,
                            const float* __restrict__ hprev) {
    int warp = (blockIdx.x * blockDim.x + threadIdx.x) >> 5;
    int lane = threadIdx.x & 31;
    if (warp >= 6 * H) return;
    const float4* row;
    const float4* vec;
    float bias;
    float* out;
    int idx;
    if (warp < 3 * H) {
        idx = warp;
        row = (const float4*)(w_ih + (size_t)idx * H);
        vec = (const float4*)g_x;
        bias = b_ih[idx];
        out = g_gi;
    } else {
        idx = warp - 3 * H;
        row = (const float4*)(w_hh + (size_t)idx * H);
        vec = (const float4*)hprev;
        bias = b_hh[idx];
        out = g_gh;
    }
    float s = 0.f;
#pragma unroll
    for (int i = 0; i < 8; i++) {
        float4 a = row[lane + 32 * i];
        float4 b = vec[lane + 32 * i];
        s += a.x * b.x + a.y * b.y + a.z * b.z + a.w * b.w;
    }
    s = warp_sum(s);
    if (lane == 0) out[idx] = s + bias;
}

// ---------------- K7: GRU gates + residual ----------------
__global__ void k7_gru(const float* __restrict__ hprev, float* __restrict__ d_out) {
    int i = threadIdx.x;
    float r = 1.f / (1.f + expf(-(g_gi[i] + g_gh[i])));
    float z = 1.f / (1.f + expf(-(g_gi[H + i] + g_gh[H + i])));
    float n = tanhf(g_gi[2 * H + i] + r * g_gh[2 * H + i]);
    float hp = hprev[i];
    float h = (1.f - z) * n + z * hp;
    d_out[V + i] = h;
    g_ov[i] = g_context[i] + h;
}

// ---------------- K8: logits = outW @ ov + outb ----------------
__global__ void __launch_bounds__(256) k8_logits(const float* __restrict__ outW,
                                                 const float* __restrict__ outb,
                                                 float* __restrict__ d_out) {
    __shared__ float4 ov[H / 4];
    int t = threadIdx.x;
    ov[t] = ((const float4*)g_ov)[t];
    __syncthreads();
    int warp = t >> 5, lane = t & 31;
    int v = blockIdx.x * 8 + warp;
    const float4* w4 = (const float4*)(outW + (size_t)v * H);
    float s = 0.f;
#pragma unroll
    for (int i = 0; i < 8; i++) {
        float4 a = w4[lane + 32 * i];
        float4 b = ov[lane + 32 * i];
        s += a.x * b.x + a.y * b.y + a.z * b.z + a.w * b.w;
    }
    s = warp_sum(s);
    if (lane == 0) d_out[v] = s + outb[v];
}

// ---------------- launch ----------------
extern "C" void kernel_launch(void* const* d_in, const int* in_sizes, int n_in,
                              void* d_out, int out_size) {
    const int* tok = (const int*)d_in[0];
    const float* hidden = (const float*)d_in[1];
    const float* enc = (const float*)d_in[2];
    const float* emb = (const float*)d_in[3];
    const float* wW = (const float*)d_in[4];
    const float* wb = (const float*)d_in[5];
    const float* uW = (const float*)d_in[6];
    const float* ub = (const float*)d_in[7];
    const float* vW = (const float*)d_in[8];
    const float* cW = (const float*)d_in[9];
    const float* cb = (const float*)d_in[10];
    const float* w_ih = (const float*)d_in[11];
    const float* b_ih = (const float*)d_in[12];
    const float* w_hh = (const float*)d_in[13];
    const float* b_hh = (const float*)d_in[14];
    const float* outW = (const float*)d_in[15];
    const float* outb = (const float*)d_in[16];
    float* out = (float*)d_out;

    cudaFuncSetAttribute(k2_scores, cudaFuncAttributeMaxDynamicSharedMemorySize, SMEM_DYN);

    k_conv_enc<<<(L * H) / 256, 256>>>(enc);
    k_conv_uW<<<(H * H) / 256, 256>>>(uW);
    k_zero<<<1, 1024>>>();
    k1_q<<<128, 256>>>(hidden, wW, wb, ub);
    k2_scores<<<dim3(L / 128, H / 128), 256, SMEM_DYN>>>(vW);
    k3_softmax<<<1, 1024>>>(out + V + H);
    k4_context<<<L / 64, 1024>>>(enc);
    k5_combine<<<128, 256>>>(cW, cb, emb, tok);
    k6_gru_gemv<<<(6 * H) / 8, 256>>>(w_ih, b_ih, w_hh, b_hh, hidden);
    k7_gru<<<1, 1024>>>(hidden, out);
    k8_logits<<<V / 8, 256>>>(outW, outb, out);
}